// round 1
// baseline (speedup 1.0000x reference)
#include <cuda_runtime.h>
#include <math.h>

#define DIM   2048
#define NH    16
#define HD    128
#define HD2   256
#define ROPE  64
#define BB    2
#define SS    2048
#define MS    (BB*SS)        // 4096 rows
#define INNER (2*NH*HD)      // 4096
#define LAMBDA_INIT 0.7836057665316244f
#define EPSV  1e-5f

// ---------------- scratch (static device memory; no allocations) -------------
__device__ float d_Q[(size_t)MS*INNER];
__device__ float d_K[(size_t)MS*INNER];
__device__ float d_V[(size_t)MS*INNER];
__device__ float d_O[(size_t)MS*INNER];
__device__ float d_lam[NH];

// ---------------- SGEMM NT: C[M,N] = A[M,K] * B[N,K]^T -----------------------
// 128x128 tile, BK=8, 256 threads, 8x8 micro-tile per thread.
__global__ __launch_bounds__(256) void sgemm_nt(
    const float* __restrict__ A, const float* __restrict__ Bm,
    float* __restrict__ C, int M, int N, int K)
{
    __shared__ float As[8][132];
    __shared__ float Bs[8][132];

    const int tid = threadIdx.x;
    const int m0 = blockIdx.y * 128;
    const int n0 = blockIdx.x * 128;
    const int tx = tid & 15;         // 0..15
    const int ty = tid >> 4;         // 0..15
    const int lrow = tid >> 1;       // 0..127
    const int lk   = (tid & 1) * 4;  // 0 or 4

    const float* Ap = A + (size_t)(m0 + lrow) * K + lk;
    const float* Bp = Bm + (size_t)(n0 + lrow) * K + lk;

    float acc[8][8];
#pragma unroll
    for (int i = 0; i < 8; i++)
#pragma unroll
        for (int j = 0; j < 8; j++) acc[i][j] = 0.f;

    for (int k0 = 0; k0 < K; k0 += 8) {
        float4 av = *(const float4*)(Ap + k0);
        float4 bv = *(const float4*)(Bp + k0);
        __syncthreads();
        As[lk+0][lrow] = av.x; As[lk+1][lrow] = av.y;
        As[lk+2][lrow] = av.z; As[lk+3][lrow] = av.w;
        Bs[lk+0][lrow] = bv.x; Bs[lk+1][lrow] = bv.y;
        Bs[lk+2][lrow] = bv.z; Bs[lk+3][lrow] = bv.w;
        __syncthreads();
#pragma unroll
        for (int kk = 0; kk < 8; kk++) {
            float a[8], b[8];
            *(float4*)(a)   = *(const float4*)&As[kk][ty*8];
            *(float4*)(a+4) = *(const float4*)&As[kk][ty*8+4];
            *(float4*)(b)   = *(const float4*)&Bs[kk][tx*8];
            *(float4*)(b+4) = *(const float4*)&Bs[kk][tx*8+4];
#pragma unroll
            for (int i = 0; i < 8; i++)
#pragma unroll
                for (int j = 0; j < 8; j++)
                    acc[i][j] = fmaf(a[i], b[j], acc[i][j]);
        }
    }

#pragma unroll
    for (int i = 0; i < 8; i++) {
        float* Cp = C + (size_t)(m0 + ty*8 + i) * N + n0 + tx*8;
        *(float4*)(Cp)   = make_float4(acc[i][0], acc[i][1], acc[i][2], acc[i][3]);
        *(float4*)(Cp+4) = make_float4(acc[i][4], acc[i][5], acc[i][6], acc[i][7]);
    }
}

// ---------------- RoPE on Q and K (first 64 dims of each 128-half) -----------
__global__ void rope_kernel(float* __restrict__ Q, float* __restrict__ K,
                            const float* __restrict__ cosp, const float* __restrict__ sinp)
{
    int i = blockIdx.x * blockDim.x + threadIdx.x;
    const int total = 2 * BB * SS * NH * 2 * (ROPE/2); // 2^23
    if (i >= total) return;
    int p    = i & 31;   i >>= 5;
    int half = i & 1;    i >>= 1;
    int h    = i & 15;   i >>= 4;
    int s    = i & 2047; i >>= 11;
    int b    = i & 1;    i >>= 1;
    float* T = i ? K : Q;
    int row = b * SS + s;
    int col = h * HD2 + half * HD + 2 * p;
    float* x = T + (size_t)row * INNER + col;
    float c  = cosp[s*32 + p];
    float sn = sinp[s*32 + p];
    float xr = x[0], xi = x[1];
    x[0] = xr*c - xi*sn;
    x[1] = xr*sn + xi*c;
}

// ---------------- lambda per head --------------------------------------------
__global__ void lam_kernel(const float* __restrict__ lq1, const float* __restrict__ lk1,
                           const float* __restrict__ lq2, const float* __restrict__ lk2)
{
    int h = blockIdx.x;
    int t = threadIdx.x;  // 128
    __shared__ float sh1[128], sh2[128];
    sh1[t] = lq1[h*HD + t] * lk1[h*HD + t];
    sh2[t] = lq2[h*HD + t] * lk2[h*HD + t];
    __syncthreads();
    for (int off = 64; off; off >>= 1) {
        if (t < off) { sh1[t] += sh1[t+off]; sh2[t] += sh2[t+off]; }
        __syncthreads();
    }
    if (t == 0) d_lam[h] = expf(sh1[0]) - expf(sh2[0]) + LAMBDA_INIT;
}

// ---------------- fused differential flash attention + RMS norm --------------
// grid: (S/32, B*NH); block: 256 threads.
// Each block: 32 query rows for one (b,h). Two online softmaxes (s1, s2),
// two V-accumulators, epilogue: o1/l1 - lam*o2/l2, RMS norm, rms_scale*(1-li).
#define QT 32
#define KT 32
#define QPAD 260
#define SPAD 33

__global__ __launch_bounds__(256) void attn_kernel(const float* __restrict__ rms_scale)
{
    extern __shared__ float smem[];
    float* qs  = smem;                    // [32][260]  (q1 cols 0..127, q2 cols 128..255)
    float* ks  = qs  + 32*QPAD;           // [32][260]
    float* vs  = ks  + 32*QPAD;           // [32][260]
    float* s1s = vs  + 32*QPAD;           // [32][33]
    float* s2s = s1s + 32*SPAD;           // [32][33]
    float* m1  = s2s + 32*SPAD;
    float* l1  = m1 + 32;
    float* f1  = l1 + 32;
    float* m2  = f1 + 32;
    float* l2  = m2 + 32;
    float* f2  = l2 + 32;

    const int qt  = blockIdx.x;
    const int bh  = blockIdx.y;
    const int b   = bh / NH;
    const int h   = bh % NH;
    const int tid = threadIdx.x;
    const int r   = tid >> 3;     // 0..31 query row in tile
    const int cg  = tid & 7;      // col group

    const size_t qbase = (size_t)(b*SS + qt*QT) * INNER + h*HD2;

    // load q tile (32 x 256)
    for (int i = tid; i < 32*64; i += 256) {
        int rr = i >> 6, cc = (i & 63) << 2;
        *(float4*)&qs[rr*QPAD + cc] = *(const float4*)&d_Q[qbase + (size_t)rr*INNER + cc];
    }
    if (tid < 32) { m1[tid] = -1e30f; l1[tid] = 0.f; m2[tid] = -1e30f; l2[tid] = 0.f; }

    float o1[32], o2[32];
#pragma unroll
    for (int i = 0; i < 32; i++) { o1[i] = 0.f; o2[i] = 0.f; }

    const float scale = 0.088388347648318447f; // 128^-0.5
    const int qg = qt*QT + r;

    for (int kt = 0; kt <= qt; kt++) {
        __syncthreads();
        const size_t kbase = (size_t)(b*SS + kt*KT) * INNER + h*HD2;
        for (int i = tid; i < 32*64; i += 256) {
            int rr = i >> 6, cc = (i & 63) << 2;
            *(float4*)&ks[rr*QPAD + cc] = *(const float4*)&d_K[kbase + (size_t)rr*INNER + cc];
            *(float4*)&vs[rr*QPAD + cc] = *(const float4*)&d_V[kbase + (size_t)rr*INNER + cc];
        }
        __syncthreads();

        // scores: thread computes s[r][cg + 8j] for j = 0..3
        {
            float a1[4] = {0,0,0,0}, a2[4] = {0,0,0,0};
            for (int d = 0; d < HD; d += 4) {
                float4 q1v = *(const float4*)&qs[r*QPAD + d];
                float4 q2v = *(const float4*)&qs[r*QPAD + HD + d];
#pragma unroll
                for (int j = 0; j < 4; j++) {
                    int kr = cg + 8*j;
                    float4 k1v = *(const float4*)&ks[kr*QPAD + d];
                    float4 k2v = *(const float4*)&ks[kr*QPAD + HD + d];
                    a1[j] += q1v.x*k1v.x + q1v.y*k1v.y + q1v.z*k1v.z + q1v.w*k1v.w;
                    a2[j] += q2v.x*k2v.x + q2v.y*k2v.y + q2v.z*k2v.z + q2v.w*k2v.w;
                }
            }
#pragma unroll
            for (int j = 0; j < 4; j++) {
                int kc = cg + 8*j;
                int kgl = kt*KT + kc;
                float msk = (kgl <= qg) ? 0.f : -1e30f;
                s1s[r*SPAD + kc] = a1[j]*scale + msk;
                s2s[r*SPAD + kc] = a2[j]*scale + msk;
            }
        }
        __syncthreads();

        // online softmax stats: warp w handles rows w, w+8, w+16, w+24
        {
            int w = tid >> 5, lane = tid & 31;
            for (int rr = w; rr < 32; rr += 8) {
                float v1 = s1s[rr*SPAD + lane];
                float v2 = s2s[rr*SPAD + lane];
                float mt1 = v1, mt2 = v2;
#pragma unroll
                for (int o = 16; o; o >>= 1) {
                    mt1 = fmaxf(mt1, __shfl_xor_sync(0xffffffffu, mt1, o));
                    mt2 = fmaxf(mt2, __shfl_xor_sync(0xffffffffu, mt2, o));
                }
                float mo1 = m1[rr], mo2 = m2[rr];
                float mn1 = fmaxf(mo1, mt1), mn2 = fmaxf(mo2, mt2);
                float p1 = __expf(v1 - mn1), p2 = __expf(v2 - mn2);
                float su1 = p1, su2 = p2;
#pragma unroll
                for (int o = 16; o; o >>= 1) {
                    su1 += __shfl_xor_sync(0xffffffffu, su1, o);
                    su2 += __shfl_xor_sync(0xffffffffu, su2, o);
                }
                s1s[rr*SPAD + lane] = p1;
                s2s[rr*SPAD + lane] = p2;
                if (lane == 0) {
                    float fo1 = __expf(mo1 - mn1);
                    float fo2 = __expf(mo2 - mn2);
                    f1[rr] = fo1; f2[rr] = fo2;
                    l1[rr] = l1[rr]*fo1 + su1;
                    l2[rr] = l2[rr]*fo2 + su2;
                    m1[rr] = mn1; m2[rr] = mn2;
                }
            }
        }
        __syncthreads();

        // accumulate: thread owns cols cg*4 + 32*chunk (chunk 0..7), 4 each
        {
            float fa = f1[r], fb = f2[r];
#pragma unroll
            for (int i = 0; i < 32; i++) { o1[i] *= fa; o2[i] *= fb; }
            for (int j = 0; j < 32; j++) {
                float p1 = s1s[r*SPAD + j];
                float p2 = s2s[r*SPAD + j];
#pragma unroll
                for (int ch = 0; ch < 8; ch++) {
                    float4 vv = *(const float4*)&vs[j*QPAD + cg*4 + ch*32];
                    o1[ch*4+0] = fmaf(p1, vv.x, o1[ch*4+0]);
                    o1[ch*4+1] = fmaf(p1, vv.y, o1[ch*4+1]);
                    o1[ch*4+2] = fmaf(p1, vv.z, o1[ch*4+2]);
                    o1[ch*4+3] = fmaf(p1, vv.w, o1[ch*4+3]);
                    o2[ch*4+0] = fmaf(p2, vv.x, o2[ch*4+0]);
                    o2[ch*4+1] = fmaf(p2, vv.y, o2[ch*4+1]);
                    o2[ch*4+2] = fmaf(p2, vv.z, o2[ch*4+2]);
                    o2[ch*4+3] = fmaf(p2, vv.w, o2[ch*4+3]);
                }
            }
        }
    }
    __syncthreads();

    // epilogue: differential combine + RMS norm + scale, write to d_O
    const float inv1 = 1.f / l1[r];
    const float inv2 = 1.f / l2[r];
    const float lam  = d_lam[h];
    float ssq = 0.f;
#pragma unroll
    for (int i = 0; i < 32; i++) {
        float v = o1[i]*inv1 - lam*o2[i]*inv2;
        o1[i] = v;
        ssq += v*v;
    }
    s1s[r*SPAD + cg] = ssq;
    __syncthreads();
    if (cg == 0) {
        float t = 0.f;
#pragma unroll
        for (int j = 0; j < 8; j++) t += s1s[r*SPAD + j];
        f1[r] = rsqrtf(t * (1.f/256.f) + EPSV);
    }
    __syncthreads();
    const float rn = f1[r] * (1.f - LAMBDA_INIT);
    const size_t obase = (size_t)(b*SS + qg) * INNER + h*HD2;
#pragma unroll
    for (int ch = 0; ch < 8; ch++) {
        int c = cg*4 + ch*32;
        float4 sc = *(const float4*)&rms_scale[h*HD2 + c];
        float4 ov = make_float4(o1[ch*4+0]*rn*sc.x, o1[ch*4+1]*rn*sc.y,
                                o1[ch*4+2]*rn*sc.z, o1[ch*4+3]*rn*sc.w);
        *(float4*)&d_O[obase + c] = ov;
    }
}

// ---------------- launch ------------------------------------------------------
extern "C" void kernel_launch(void* const* d_in, const int* in_sizes, int n_in,
                              void* d_out, int out_size)
{
    const float* x    = (const float*)d_in[0];
    const float* w_q  = (const float*)d_in[1];
    const float* w_k  = (const float*)d_in[2];
    const float* w_v  = (const float*)d_in[3];
    const float* w_o  = (const float*)d_in[4];
    const float* lq1  = (const float*)d_in[5];
    const float* lk1  = (const float*)d_in[6];
    const float* lq2  = (const float*)d_in[7];
    const float* lk2  = (const float*)d_in[8];
    const float* rsc  = (const float*)d_in[9];
    const float* fcos = (const float*)d_in[10];
    const float* fsin = (const float*)d_in[11];
    float* out = (float*)d_out;

    float *Q, *K, *V, *O;
    cudaGetSymbolAddress((void**)&Q, d_Q);
    cudaGetSymbolAddress((void**)&K, d_K);
    cudaGetSymbolAddress((void**)&V, d_V);
    cudaGetSymbolAddress((void**)&O, d_O);

    // QKV projections
    dim3 gq(INNER/128, MS/128);
    sgemm_nt<<<gq, 256>>>(x, w_q, Q, MS, INNER, DIM);
    sgemm_nt<<<gq, 256>>>(x, w_k, K, MS, INNER, DIM);
    sgemm_nt<<<gq, 256>>>(x, w_v, V, MS, INNER, DIM);

    // RoPE (Q and K)
    const int rope_total = 2 * BB * SS * NH * 2 * (ROPE/2);
    rope_kernel<<<rope_total/256, 256>>>(Q, K, fcos, fsin);

    // per-head lambda
    lam_kernel<<<NH, 128>>>(lq1, lk1, lq2, lk2);

    // fused differential attention + RMS norm
    const int ATT_SMEM = (3*32*QPAD + 2*32*SPAD + 6*32) * (int)sizeof(float);
    cudaFuncSetAttribute(attn_kernel, cudaFuncAttributeMaxDynamicSharedMemorySize, ATT_SMEM);
    attn_kernel<<<dim3(SS/QT, BB*NH), 256, ATT_SMEM>>>(rsc);

    // output projection
    dim3 go(DIM/128, MS/128);
    sgemm_nt<<<go, 256>>>(O, w_o, out, MS, DIM, INNER);
}

// round 3
// speedup vs baseline: 1.6130x; 1.6130x over previous
#include <cuda_runtime.h>
#include <math.h>
#include <cstdint>

#define DIM   2048
#define NH    16
#define HD    128
#define HD2   256
#define ROPE  64
#define BB    2
#define SS    2048
#define MS    (BB*SS)        // 4096 rows
#define INNER (2*NH*HD)      // 4096
#define LAMBDA_INIT 0.7836057665316244f
#define EPSV  1e-5f

// ---------------- scratch (static device memory; no allocations) -------------
__device__ float d_Q[(size_t)MS*INNER];
__device__ float d_K[(size_t)MS*INNER];
__device__ float d_V[(size_t)MS*INNER];
__device__ float d_O[(size_t)MS*INNER];
__device__ float d_lam[NH];

// ---------------- helpers -----------------------------------------------------
__device__ __forceinline__ uint32_t f2tf(float f) {
    uint32_t u;
    asm("cvt.rna.tf32.f32 %0, %1;" : "=r"(u) : "f"(f));
    return u;
}

__device__ __forceinline__ uint32_t cvta_smem(const void* p) {
    uint32_t a;
    asm("{ .reg .u64 t; cvta.to.shared.u64 t, %1; cvt.u32.u64 %0, t; }" : "=r"(a) : "l"(p));
    return a;
}

// ---------------- tf32 mma.sync GEMM NT: C[M,N] = A[M,K] * B[N,K]^T ------------
// CTA 128x128, BK=32, 256 threads (8 warps, 4(M) x 2(N)), warp tile 32x64.
// cp.async double-buffered fp32 smem (pitch 36 floats), cvt.rna.tf32 at frag load.
#define BM 128
#define BN 128
#define BK 32
#define PITCH 36
#define STG (BM*PITCH)                       // floats per A (or B) stage: 4608
#define GEMM_SMEM (4*STG*(int)sizeof(float)) // 73728 bytes

__global__ __launch_bounds__(256, 1) void gemm_mma(
    const float* __restrict__ A, const float* __restrict__ B, float* __restrict__ C,
    int M, int N, int K)
{
    extern __shared__ float sm[];
    float* As = sm;            // [2][128][36]
    float* Bs = sm + 2*STG;    // [2][128][36]

    const int tid  = threadIdx.x;
    const int wid  = tid >> 5;
    const int lane = tid & 31;
    const int wm   = wid & 3;      // 0..3  (M warps)
    const int wn   = wid >> 2;     // 0..1  (N warps)
    const int g    = lane >> 2;    // 0..7
    const int t4   = lane & 3;     // 0..3
    const int m0 = blockIdx.y * BM;
    const int n0 = blockIdx.x * BN;
    const int nk = K / BK;

    float c[2][8][4];
#pragma unroll
    for (int t = 0; t < 2; t++)
#pragma unroll
        for (int n = 0; n < 8; n++)
#pragma unroll
            for (int j = 0; j < 4; j++) c[t][n][j] = 0.f;

    const uint32_t asb = cvta_smem(As);
    const uint32_t bsb = cvta_smem(Bs);

    // cp.async one BK stage (A: 128x32 fp32, B: 128x32 fp32), 8 x 16B per thread
#define LOAD_STAGE(s, kb) do { \
    _Pragma("unroll") \
    for (int it = 0; it < 4; it++) { \
        int ch = tid + it * 256; \
        int row = ch >> 3, q = ch & 7; \
        const float* srcA = A + (size_t)(m0 + row) * K + (kb) + q * 4; \
        uint32_t dstA = asb + ((s) * STG + row * PITCH + q * 4) * 4; \
        asm volatile("cp.async.cg.shared.global [%0], [%1], 16;" :: "r"(dstA), "l"(srcA)); \
        const float* srcB = B + (size_t)(n0 + row) * K + (kb) + q * 4; \
        uint32_t dstB = bsb + ((s) * STG + row * PITCH + q * 4) * 4; \
        asm volatile("cp.async.cg.shared.global [%0], [%1], 16;" :: "r"(dstB), "l"(srcB)); \
    } \
    asm volatile("cp.async.commit_group;"); \
} while (0)

    LOAD_STAGE(0, 0);

    for (int i = 0; i < nk; i++) {
        const int s = i & 1;
        if (i + 1 < nk) {
            LOAD_STAGE((i + 1) & 1, (i + 1) * BK);
            asm volatile("cp.async.wait_group 1;");
        } else {
            asm volatile("cp.async.wait_group 0;");
        }
        __syncthreads();

        const float* Abase = As + s * STG + (wm * 32 + g) * PITCH;
        const float* Bbase = Bs + s * STG + (wn * 64 + g) * PITCH;
#pragma unroll
        for (int kk = 0; kk < 4; kk++) {
            const int k0 = kk * 8 + t4;
            uint32_t a[2][4], b[8][2];
#pragma unroll
            for (int t = 0; t < 2; t++) {
                const float* p = Abase + t * 16 * PITCH + k0;
                a[t][0] = f2tf(p[0]);
                a[t][1] = f2tf(p[8 * PITCH]);
                a[t][2] = f2tf(p[4]);
                a[t][3] = f2tf(p[8 * PITCH + 4]);
            }
#pragma unroll
            for (int n = 0; n < 8; n++) {
                const float* p = Bbase + n * 8 * PITCH + k0;
                // b frag is indexed by (k=t4, n=g): swap roles -> use row (wn*64+n*8+g), col k0
                b[n][0] = f2tf(p[0]);
                b[n][1] = f2tf(p[4]);
            }
#pragma unroll
            for (int t = 0; t < 2; t++)
#pragma unroll
                for (int n = 0; n < 8; n++) {
                    asm volatile(
                        "mma.sync.aligned.m16n8k8.row.col.f32.tf32.tf32.f32 "
                        "{%0,%1,%2,%3}, {%4,%5,%6,%7}, {%8,%9}, {%0,%1,%2,%3};"
                        : "+f"(c[t][n][0]), "+f"(c[t][n][1]), "+f"(c[t][n][2]), "+f"(c[t][n][3])
                        : "r"(a[t][0]), "r"(a[t][1]), "r"(a[t][2]), "r"(a[t][3]),
                          "r"(b[n][0]), "r"(b[n][1]));
                }
        }
        __syncthreads();
    }

    // epilogue
#pragma unroll
    for (int t = 0; t < 2; t++) {
        const int row = m0 + wm * 32 + t * 16 + g;
#pragma unroll
        for (int n = 0; n < 8; n++) {
            const int col = n0 + wn * 64 + n * 8 + t4 * 2;
            *(float2*)&C[(size_t)row * N + col]       = make_float2(c[t][n][0], c[t][n][1]);
            *(float2*)&C[(size_t)(row + 8) * N + col] = make_float2(c[t][n][2], c[t][n][3]);
        }
    }
}

// ---------------- RoPE on Q and K (first 64 dims of each 128-half) -----------
__global__ void rope_kernel(float* __restrict__ Q, float* __restrict__ K,
                            const float* __restrict__ cosp, const float* __restrict__ sinp)
{
    int i = blockIdx.x * blockDim.x + threadIdx.x;
    const int total = 2 * BB * SS * NH * 2 * (ROPE/2); // 2^23
    if (i >= total) return;
    int p    = i & 31;   i >>= 5;
    int half = i & 1;    i >>= 1;
    int h    = i & 15;   i >>= 4;
    int s    = i & 2047; i >>= 11;
    int b    = i & 1;    i >>= 1;
    float* T = i ? K : Q;
    int row = b * SS + s;
    int col = h * HD2 + half * HD + 2 * p;
    float* x = T + (size_t)row * INNER + col;
    float c  = cosp[s*32 + p];
    float sn = sinp[s*32 + p];
    float xr = x[0], xi = x[1];
    x[0] = xr*c - xi*sn;
    x[1] = xr*sn + xi*c;
}

// ---------------- lambda per head --------------------------------------------
__global__ void lam_kernel(const float* __restrict__ lq1, const float* __restrict__ lk1,
                           const float* __restrict__ lq2, const float* __restrict__ lk2)
{
    int h = blockIdx.x;
    int t = threadIdx.x;  // 128
    __shared__ float sh1[128], sh2[128];
    sh1[t] = lq1[h*HD + t] * lk1[h*HD + t];
    sh2[t] = lq2[h*HD + t] * lk2[h*HD + t];
    __syncthreads();
    for (int off = 64; off; off >>= 1) {
        if (t < off) { sh1[t] += sh1[t+off]; sh2[t] += sh2[t+off]; }
        __syncthreads();
    }
    if (t == 0) d_lam[h] = expf(sh1[0]) - expf(sh2[0]) + LAMBDA_INIT;
}

// ---------------- fused differential flash attention + RMS norm --------------
#define QT 32
#define KT 32
#define QPAD 260
#define SPAD 33

__global__ __launch_bounds__(256) void attn_kernel(const float* __restrict__ rms_scale)
{
    extern __shared__ float smemf[];
    float* qs  = smemf;                   // [32][260]
    float* ks  = qs  + 32*QPAD;           // [32][260]
    float* vs  = ks  + 32*QPAD;           // [32][260]
    float* s1s = vs  + 32*QPAD;           // [32][33]
    float* s2s = s1s + 32*SPAD;           // [32][33]
    float* m1  = s2s + 32*SPAD;
    float* l1  = m1 + 32;
    float* f1  = l1 + 32;
    float* m2  = f1 + 32;
    float* l2  = m2 + 32;
    float* f2  = l2 + 32;

    const int qt  = blockIdx.x;
    const int bh  = blockIdx.y;
    const int b   = bh / NH;
    const int h   = bh % NH;
    const int tid = threadIdx.x;
    const int r   = tid >> 3;
    const int cg  = tid & 7;

    const size_t qbase = (size_t)(b*SS + qt*QT) * INNER + h*HD2;

    for (int i = tid; i < 32*64; i += 256) {
        int rr = i >> 6, cc = (i & 63) << 2;
        *(float4*)&qs[rr*QPAD + cc] = *(const float4*)&d_Q[qbase + (size_t)rr*INNER + cc];
    }
    if (tid < 32) { m1[tid] = -1e30f; l1[tid] = 0.f; m2[tid] = -1e30f; l2[tid] = 0.f; }

    float o1[32], o2[32];
#pragma unroll
    for (int i = 0; i < 32; i++) { o1[i] = 0.f; o2[i] = 0.f; }

    const float scale = 0.088388347648318447f;
    const int qg = qt*QT + r;

    for (int kt = 0; kt <= qt; kt++) {
        __syncthreads();
        const size_t kbase = (size_t)(b*SS + kt*KT) * INNER + h*HD2;
        for (int i = tid; i < 32*64; i += 256) {
            int rr = i >> 6, cc = (i & 63) << 2;
            *(float4*)&ks[rr*QPAD + cc] = *(const float4*)&d_K[kbase + (size_t)rr*INNER + cc];
            *(float4*)&vs[rr*QPAD + cc] = *(const float4*)&d_V[kbase + (size_t)rr*INNER + cc];
        }
        __syncthreads();

        {
            float a1[4] = {0,0,0,0}, a2[4] = {0,0,0,0};
            for (int d = 0; d < HD; d += 4) {
                float4 q1v = *(const float4*)&qs[r*QPAD + d];
                float4 q2v = *(const float4*)&qs[r*QPAD + HD + d];
#pragma unroll
                for (int j = 0; j < 4; j++) {
                    int kr = cg + 8*j;
                    float4 k1v = *(const float4*)&ks[kr*QPAD + d];
                    float4 k2v = *(const float4*)&ks[kr*QPAD + HD + d];
                    a1[j] += q1v.x*k1v.x + q1v.y*k1v.y + q1v.z*k1v.z + q1v.w*k1v.w;
                    a2[j] += q2v.x*k2v.x + q2v.y*k2v.y + q2v.z*k2v.z + q2v.w*k2v.w;
                }
            }
#pragma unroll
            for (int j = 0; j < 4; j++) {
                int kc = cg + 8*j;
                int kgl = kt*KT + kc;
                float msk = (kgl <= qg) ? 0.f : -1e30f;
                s1s[r*SPAD + kc] = a1[j]*scale + msk;
                s2s[r*SPAD + kc] = a2[j]*scale + msk;
            }
        }
        __syncthreads();

        {
            int w = tid >> 5, lane = tid & 31;
            for (int rr = w; rr < 32; rr += 8) {
                float v1 = s1s[rr*SPAD + lane];
                float v2 = s2s[rr*SPAD + lane];
                float mt1 = v1, mt2 = v2;
#pragma unroll
                for (int o = 16; o; o >>= 1) {
                    mt1 = fmaxf(mt1, __shfl_xor_sync(0xffffffffu, mt1, o));
                    mt2 = fmaxf(mt2, __shfl_xor_sync(0xffffffffu, mt2, o));
                }
                float mo1 = m1[rr], mo2 = m2[rr];
                float mn1 = fmaxf(mo1, mt1), mn2 = fmaxf(mo2, mt2);
                float p1 = __expf(v1 - mn1), p2 = __expf(v2 - mn2);
                float su1 = p1, su2 = p2;
#pragma unroll
                for (int o = 16; o; o >>= 1) {
                    su1 += __shfl_xor_sync(0xffffffffu, su1, o);
                    su2 += __shfl_xor_sync(0xffffffffu, su2, o);
                }
                s1s[rr*SPAD + lane] = p1;
                s2s[rr*SPAD + lane] = p2;
                if (lane == 0) {
                    float fo1 = __expf(mo1 - mn1);
                    float fo2 = __expf(mo2 - mn2);
                    f1[rr] = fo1; f2[rr] = fo2;
                    l1[rr] = l1[rr]*fo1 + su1;
                    l2[rr] = l2[rr]*fo2 + su2;
                    m1[rr] = mn1; m2[rr] = mn2;
                }
            }
        }
        __syncthreads();

        {
            float fa = f1[r], fb = f2[r];
#pragma unroll
            for (int i = 0; i < 32; i++) { o1[i] *= fa; o2[i] *= fb; }
            for (int j = 0; j < 32; j++) {
                float p1 = s1s[r*SPAD + j];
                float p2 = s2s[r*SPAD + j];
#pragma unroll
                for (int ch = 0; ch < 8; ch++) {
                    float4 vv = *(const float4*)&vs[j*QPAD + cg*4 + ch*32];
                    o1[ch*4+0] = fmaf(p1, vv.x, o1[ch*4+0]);
                    o1[ch*4+1] = fmaf(p1, vv.y, o1[ch*4+1]);
                    o1[ch*4+2] = fmaf(p1, vv.z, o1[ch*4+2]);
                    o1[ch*4+3] = fmaf(p1, vv.w, o1[ch*4+3]);
                    o2[ch*4+0] = fmaf(p2, vv.x, o2[ch*4+0]);
                    o2[ch*4+1] = fmaf(p2, vv.y, o2[ch*4+1]);
                    o2[ch*4+2] = fmaf(p2, vv.z, o2[ch*4+2]);
                    o2[ch*4+3] = fmaf(p2, vv.w, o2[ch*4+3]);
                }
            }
        }
    }
    __syncthreads();

    const float inv1 = 1.f / l1[r];
    const float inv2 = 1.f / l2[r];
    const float lam  = d_lam[h];
    float ssq = 0.f;
#pragma unroll
    for (int i = 0; i < 32; i++) {
        float v = o1[i]*inv1 - lam*o2[i]*inv2;
        o1[i] = v;
        ssq += v*v;
    }
    s1s[r*SPAD + cg] = ssq;
    __syncthreads();
    if (cg == 0) {
        float t = 0.f;
#pragma unroll
        for (int j = 0; j < 8; j++) t += s1s[r*SPAD + j];
        f1[r] = rsqrtf(t * (1.f/256.f) + EPSV);
    }
    __syncthreads();
    const float rn = f1[r] * (1.f - LAMBDA_INIT);
    const size_t obase = (size_t)(b*SS + qg) * INNER + h*HD2;
#pragma unroll
    for (int ch = 0; ch < 8; ch++) {
        int c = cg*4 + ch*32;
        float4 sc = *(const float4*)&rms_scale[h*HD2 + c];
        float4 ov = make_float4(o1[ch*4+0]*rn*sc.x, o1[ch*4+1]*rn*sc.y,
                                o1[ch*4+2]*rn*sc.z, o1[ch*4+3]*rn*sc.w);
        *(float4*)&d_O[obase + c] = ov;
    }
}

// ---------------- launch ------------------------------------------------------
extern "C" void kernel_launch(void* const* d_in, const int* in_sizes, int n_in,
                              void* d_out, int out_size)
{
    const float* x    = (const float*)d_in[0];
    const float* w_q  = (const float*)d_in[1];
    const float* w_k  = (const float*)d_in[2];
    const float* w_v  = (const float*)d_in[3];
    const float* w_o  = (const float*)d_in[4];
    const float* lq1  = (const float*)d_in[5];
    const float* lk1  = (const float*)d_in[6];
    const float* lq2  = (const float*)d_in[7];
    const float* lk2  = (const float*)d_in[8];
    const float* rsc  = (const float*)d_in[9];
    const float* fcos = (const float*)d_in[10];
    const float* fsin = (const float*)d_in[11];
    float* out = (float*)d_out;

    float *Q, *K, *V, *O;
    cudaGetSymbolAddress((void**)&Q, d_Q);
    cudaGetSymbolAddress((void**)&K, d_K);
    cudaGetSymbolAddress((void**)&V, d_V);
    cudaGetSymbolAddress((void**)&O, d_O);

    cudaFuncSetAttribute(gemm_mma, cudaFuncAttributeMaxDynamicSharedMemorySize, GEMM_SMEM);

    // QKV projections (tf32 mma.sync)
    dim3 gq(INNER/BN, MS/BM);
    gemm_mma<<<gq, 256, GEMM_SMEM>>>(x, w_q, Q, MS, INNER, DIM);
    gemm_mma<<<gq, 256, GEMM_SMEM>>>(x, w_k, K, MS, INNER, DIM);
    gemm_mma<<<gq, 256, GEMM_SMEM>>>(x, w_v, V, MS, INNER, DIM);

    // RoPE (Q and K)
    const int rope_total = 2 * BB * SS * NH * 2 * (ROPE/2);
    rope_kernel<<<rope_total/256, 256>>>(Q, K, fcos, fsin);

    // per-head lambda
    lam_kernel<<<NH, 128>>>(lq1, lk1, lq2, lk2);

    // fused differential attention + RMS norm
    const int ATT_SMEM = (3*32*QPAD + 2*32*SPAD + 6*32) * (int)sizeof(float);
    cudaFuncSetAttribute(attn_kernel, cudaFuncAttributeMaxDynamicSharedMemorySize, ATT_SMEM);
    attn_kernel<<<dim3(SS/QT, BB*NH), 256, ATT_SMEM>>>(rsc);

    // output projection (tf32 mma.sync)
    dim3 go(DIM/BN, MS/BM);
    gemm_mma<<<go, 256, GEMM_SMEM>>>(O, w_o, out, MS, DIM, INNER);
}